// round 1
// baseline (speedup 1.0000x reference)
#include <cuda_runtime.h>
#include <math.h>
#include <stddef.h>

#define D      1024
#define H      16
#define DH     64
#define NSEQ   2048
#define BATCH  4
#define ROWS   (BATCH*NSEQ)   /* 8192 */
#define BHN    (BATCH*H)      /* 64   */
#define TD     (3*D)          /* 3072 */

// ---------------- scratch (static device globals; no runtime allocation) ----
__device__ float g_qkv[(size_t)ROWS * TD];            //  96 MB
__device__ float g_S[(size_t)BHN * NSEQ * NSEQ];      // 1073 MB
__device__ float g_attn[(size_t)ROWS * D];            //  32 MB

// ---------------- generic NN SGEMM: C = A@B + bias --------------------------
// 128x128 block tile, BK=8, 256 threads, 8x8 per-thread micro-tile.
// Requires M%128==0, N%128==0, K%8==0, all pointers 16B aligned, ld%4==0.
__global__ __launch_bounds__(256) void sgemm_nn(
    int M, int N, int K,
    const float* __restrict__ A, int lda,
    const float* __restrict__ Bm, int ldb,
    float* __restrict__ C, int ldc,
    const float* __restrict__ bias)
{
    const int BM = 128, BN = 128, BK = 8;
    __shared__ float As[BK][BM];
    __shared__ float Bs[BK][BN];

    int tid  = threadIdx.x;
    int brow = blockIdx.y * BM;
    int bcol = blockIdx.x * BN;

    int a_r = tid >> 1;          // 0..127
    int a_c = (tid & 1) * 4;     // 0 or 4
    int b_r = tid >> 5;          // 0..7
    int b_c = (tid & 31) * 4;    // 0..124
    int ty  = tid >> 4;          // 0..15
    int tx  = tid & 15;          // 0..15

    float acc[8][8];
#pragma unroll
    for (int i = 0; i < 8; i++)
#pragma unroll
        for (int j = 0; j < 8; j++) acc[i][j] = 0.f;

    for (int k0 = 0; k0 < K; k0 += BK) {
        float4 av = *(const float4*)(A + (size_t)(brow + a_r) * lda + k0 + a_c);
        As[a_c + 0][a_r] = av.x;
        As[a_c + 1][a_r] = av.y;
        As[a_c + 2][a_r] = av.z;
        As[a_c + 3][a_r] = av.w;
        float4 bv = *(const float4*)(Bm + (size_t)(k0 + b_r) * ldb + bcol + b_c);
        *(float4*)&Bs[b_r][b_c] = bv;
        __syncthreads();

#pragma unroll
        for (int kk = 0; kk < BK; kk++) {
            float ar[8], br[8];
#pragma unroll
            for (int i = 0; i < 8; i++) ar[i] = As[kk][ty * 8 + i];
#pragma unroll
            for (int j = 0; j < 8; j++) br[j] = Bs[kk][tx * 8 + j];
#pragma unroll
            for (int i = 0; i < 8; i++)
#pragma unroll
                for (int j = 0; j < 8; j++) acc[i][j] += ar[i] * br[j];
        }
        __syncthreads();
    }

#pragma unroll
    for (int i = 0; i < 8; i++) {
        size_t r = (size_t)(brow + ty * 8 + i);
#pragma unroll
        for (int j = 0; j < 8; j += 4) {
            int c = bcol + tx * 8 + j;
            float4 o;
            o.x = acc[i][j + 0] + bias[c + 0];
            o.y = acc[i][j + 1] + bias[c + 1];
            o.z = acc[i][j + 2] + bias[c + 2];
            o.w = acc[i][j + 3] + bias[c + 3];
            *(float4*)(C + r * ldc + c) = o;
        }
    }
}

// ---------------- scores: S[bh,q,k] = (Q_bh @ K_bh^T) / 8 -------------------
// grid (32, 32, 64): x = k-tile, y = q-tile, z = b*H+h. 64x64 tile, K=64.
__global__ __launch_bounds__(256) void scores_kernel(const float* __restrict__ qkv)
{
    int bh = blockIdx.z;
    int b = bh >> 4, h = bh & 15;
    int brow = blockIdx.y * 64;   // q rows
    int bcol = blockIdx.x * 64;   // k rows

    __shared__ float Qs[64][65];
    __shared__ float Ks[64][65];

    int tid = threadIdx.x;
    const float* base = qkv + (size_t)b * NSEQ * TD + h * (3 * DH);

    for (int i = tid; i < 64 * 16; i += 256) {
        int r = i >> 4, c4 = (i & 15) * 4;
        float4 q = *(const float4*)(base + (size_t)(brow + r) * TD + c4);
        Qs[r][c4 + 0] = q.x; Qs[r][c4 + 1] = q.y;
        Qs[r][c4 + 2] = q.z; Qs[r][c4 + 3] = q.w;
        float4 k = *(const float4*)(base + (size_t)(bcol + r) * TD + DH + c4);
        Ks[r][c4 + 0] = k.x; Ks[r][c4 + 1] = k.y;
        Ks[r][c4 + 2] = k.z; Ks[r][c4 + 3] = k.w;
    }
    __syncthreads();

    int ty = tid >> 4, tx = tid & 15;
    float acc[4][4];
#pragma unroll
    for (int i = 0; i < 4; i++)
#pragma unroll
        for (int j = 0; j < 4; j++) acc[i][j] = 0.f;

#pragma unroll 8
    for (int k = 0; k < 64; k++) {
        float qr[4], kr[4];
#pragma unroll
        for (int i = 0; i < 4; i++) qr[i] = Qs[ty * 4 + i][k];
#pragma unroll
        for (int j = 0; j < 4; j++) kr[j] = Ks[tx * 4 + j][k];
#pragma unroll
        for (int i = 0; i < 4; i++)
#pragma unroll
            for (int j = 0; j < 4; j++) acc[i][j] += qr[i] * kr[j];
    }

    float* Sp = g_S + ((size_t)bh * NSEQ + brow) * NSEQ + bcol;
#pragma unroll
    for (int i = 0; i < 4; i++)
#pragma unroll
        for (int j = 0; j < 4; j++)
            Sp[(size_t)(ty * 4 + i) * NSEQ + tx * 4 + j] = acc[i][j] * 0.125f;
}

// ---------------- softmax over rows of g_S ----------------------------------
// grid 64*2048 blocks, 256 threads; 2048-wide row resident in registers.
__global__ __launch_bounds__(256) void softmax_kernel()
{
    size_t row = blockIdx.x;
    float* p = g_S + row * NSEQ;
    int tid = threadIdx.x;

    float v[8];
    float m = -1e30f;
#pragma unroll
    for (int i = 0; i < 8; i++) {
        v[i] = p[tid + (i << 8)];
        m = fmaxf(m, v[i]);
    }

    __shared__ float red[256];
    red[tid] = m;
    __syncthreads();
    for (int s = 128; s > 0; s >>= 1) {
        if (tid < s) red[tid] = fmaxf(red[tid], red[tid + s]);
        __syncthreads();
    }
    m = red[0];
    __syncthreads();

    float sum = 0.f;
#pragma unroll
    for (int i = 0; i < 8; i++) {
        v[i] = __expf(v[i] - m);
        sum += v[i];
    }
    red[tid] = sum;
    __syncthreads();
    for (int s = 128; s > 0; s >>= 1) {
        if (tid < s) red[tid] += red[tid + s];
        __syncthreads();
    }
    float inv = 1.f / red[0];

#pragma unroll
    for (int i = 0; i < 8; i++) p[tid + (i << 8)] = v[i] * inv;
}

// ---------------- PV: attn[b,n, h*64+d] = sum_k P[bh,n,k] * V[bh,k,d] -------
// grid (32, 64): x = q-tile, y = bh. Writes transposed to [b,n,D] directly.
__global__ __launch_bounds__(256) void pv_kernel(const float* __restrict__ qkv)
{
    int bh = blockIdx.y;
    int b = bh >> 4, h = bh & 15;
    int brow = blockIdx.x * 64;

    __shared__ float Ps[64][65];
    __shared__ float Vs[64][65];

    int tid = threadIdx.x;
    int ty = tid >> 4, tx = tid & 15;

    float acc[4][4];
#pragma unroll
    for (int i = 0; i < 4; i++)
#pragma unroll
        for (int j = 0; j < 4; j++) acc[i][j] = 0.f;

    const float* Sbase = g_S + ((size_t)bh * NSEQ + brow) * NSEQ;
    const float* Vbase = qkv + (size_t)b * NSEQ * TD + h * (3 * DH) + 2 * DH;

    for (int kt = 0; kt < NSEQ; kt += 64) {
        for (int i = tid; i < 64 * 16; i += 256) {
            int r = i >> 4, c4 = (i & 15) * 4;
            float4 pv = *(const float4*)(Sbase + (size_t)r * NSEQ + kt + c4);
            Ps[r][c4 + 0] = pv.x; Ps[r][c4 + 1] = pv.y;
            Ps[r][c4 + 2] = pv.z; Ps[r][c4 + 3] = pv.w;
            float4 vv = *(const float4*)(Vbase + (size_t)(kt + r) * TD + c4);
            Vs[r][c4 + 0] = vv.x; Vs[r][c4 + 1] = vv.y;
            Vs[r][c4 + 2] = vv.z; Vs[r][c4 + 3] = vv.w;
        }
        __syncthreads();

#pragma unroll 8
        for (int k = 0; k < 64; k++) {
            float pr[4], vr[4];
#pragma unroll
            for (int i = 0; i < 4; i++) pr[i] = Ps[ty * 4 + i][k];
#pragma unroll
            for (int j = 0; j < 4; j++) vr[j] = Vs[k][tx * 4 + j];
#pragma unroll
            for (int i = 0; i < 4; i++)
#pragma unroll
                for (int j = 0; j < 4; j++) acc[i][j] += pr[i] * vr[j];
        }
        __syncthreads();
    }

#pragma unroll
    for (int i = 0; i < 4; i++) {
        size_t r = (size_t)(b * NSEQ + brow + ty * 4 + i);
#pragma unroll
        for (int j = 0; j < 4; j++)
            g_attn[r * D + h * DH + tx * 4 + j] = acc[i][j];
    }
}

// ---------------- launch -----------------------------------------------------
extern "C" void kernel_launch(void* const* d_in, const int* in_sizes, int n_in,
                              void* d_out, int out_size)
{
    const float* z     = (const float*)d_in[0];  // [4,2048,1024]
    const float* W_qkv = (const float*)d_in[1];  // [1024,3072]
    const float* b_qkv = (const float*)d_in[2];  // [3072]
    const float* W_msa = (const float*)d_in[3];  // [1024,1024]
    const float* b_msa = (const float*)d_in[4];  // [1024]
    float* out = (float*)d_out;                  // [4,2048,1024]

    float *p_qkv = nullptr, *p_attn = nullptr;
    cudaGetSymbolAddress((void**)&p_qkv, g_qkv);
    cudaGetSymbolAddress((void**)&p_attn, g_attn);

    // 1) QKV projection: [8192,1024] @ [1024,3072] + bias
    sgemm_nn<<<dim3(TD / 128, ROWS / 128), 256>>>(
        ROWS, TD, D, z, D, W_qkv, TD, p_qkv, TD, b_qkv);

    // 2) scores = Q K^T / 8
    scores_kernel<<<dim3(NSEQ / 64, NSEQ / 64, BHN), 256>>>(p_qkv);

    // 3) softmax rows
    softmax_kernel<<<BHN * NSEQ, 256>>>();

    // 4) attn = P @ V (written transposed to [b,n,D])
    pv_kernel<<<dim3(NSEQ / 64, BHN), 256>>>(p_qkv);

    // 5) output projection: [8192,1024] @ [1024,1024] + bias
    sgemm_nn<<<dim3(D / 128, ROWS / 128), 256>>>(
        ROWS, D, D, p_attn, D, W_msa, D, out, D, b_msa);
}

// round 3
// speedup vs baseline: 3.2784x; 3.2784x over previous
#include <cuda_runtime.h>
#include <math.h>
#include <stddef.h>
#include <stdint.h>

#define D      1024
#define H      16
#define DH     64
#define NSEQ   2048
#define BATCH  4
#define ROWS   (BATCH*NSEQ)   /* 8192 */
#define BHN    (BATCH*H)      /* 64   */
#define TD     (3*D)          /* 3072 */

// ---------------- scratch ----------------------------------------------------
__device__ float g_qkv[(size_t)ROWS * TD];   // 96 MB
__device__ float g_attn[(size_t)ROWS * D];   // 32 MB

// ---------------- helpers ----------------------------------------------------
__device__ __forceinline__ uint32_t f2tf(float f) {
    uint32_t u;
    asm("cvt.rna.tf32.f32 %0, %1;" : "=r"(u) : "f"(f));
    return u;
}

__device__ __forceinline__ void mma_tf32(float* d, const uint32_t* a, const uint32_t* b) {
    asm volatile(
        "mma.sync.aligned.m16n8k8.row.col.f32.tf32.tf32.f32 "
        "{%0,%1,%2,%3}, {%4,%5,%6,%7}, {%8,%9}, {%0,%1,%2,%3};"
        : "+f"(d[0]), "+f"(d[1]), "+f"(d[2]), "+f"(d[3])
        : "r"(a[0]), "r"(a[1]), "r"(a[2]), "r"(a[3]), "r"(b[0]), "r"(b[1]));
}

// ---------------- tf32 tensor-core NN GEMM: C = A@B + bias -------------------
// BM=128, BN=128, BK=32, 256 threads = 8 warps (2x4), warp tile 64x32.
// Requires M%128==0, N%128==0, K%32==0. Static smem ~35.8KB.
__global__ __launch_bounds__(256) void gemm_tf32(
    int M, int N, int K,
    const float* __restrict__ A, int lda,
    const float* __restrict__ B, int ldb,
    float* __restrict__ C, int ldc,
    const float* __restrict__ bias)
{
    const int BM = 128, BN = 128, BK = 32;
    __shared__ uint32_t As[BM][BK + 4];   // stride 36 words
    __shared__ uint32_t Bs[BK][BN + 8];   // stride 136 words

    int tid  = threadIdx.x;
    int warp = tid >> 5, lane = tid & 31;
    int wm   = (warp >> 2) * 64;
    int wn   = (warp & 3) * 32;
    int bm   = blockIdx.y * BM;
    int bn   = blockIdx.x * BN;
    int q    = lane & 3;     // thread-in-group
    int r    = lane >> 2;    // group id

    float acc[4][4][4];
#pragma unroll
    for (int mt = 0; mt < 4; mt++)
#pragma unroll
        for (int nt = 0; nt < 4; nt++)
#pragma unroll
            for (int i = 0; i < 4; i++) acc[mt][nt][i] = 0.f;

    int arow = tid >> 1;          // 0..127
    int acol = (tid & 1) * 16;    // 0 / 16
    int brow = tid >> 3;          // 0..31
    int bcol = (tid & 7) * 16;    // 0..112

    for (int k0 = 0; k0 < K; k0 += BK) {
        __syncthreads();
        const float* Ap = A + (size_t)(bm + arow) * lda + k0 + acol;
#pragma unroll
        for (int i = 0; i < 4; i++) {
            float4 v = *(const float4*)(Ap + i * 4);
            As[arow][acol + i * 4 + 0] = f2tf(v.x);
            As[arow][acol + i * 4 + 1] = f2tf(v.y);
            As[arow][acol + i * 4 + 2] = f2tf(v.z);
            As[arow][acol + i * 4 + 3] = f2tf(v.w);
        }
        const float* Bp = B + (size_t)(k0 + brow) * ldb + bn + bcol;
#pragma unroll
        for (int i = 0; i < 4; i++) {
            float4 v = *(const float4*)(Bp + i * 4);
            Bs[brow][bcol + i * 4 + 0] = f2tf(v.x);
            Bs[brow][bcol + i * 4 + 1] = f2tf(v.y);
            Bs[brow][bcol + i * 4 + 2] = f2tf(v.z);
            Bs[brow][bcol + i * 4 + 3] = f2tf(v.w);
        }
        __syncthreads();

#pragma unroll
        for (int ks = 0; ks < 4; ks++) {
            int k = ks * 8;
            uint32_t a[4][4];
#pragma unroll
            for (int mt = 0; mt < 4; mt++) {
                int rb = wm + mt * 16;
                a[mt][0] = As[rb + r][k + q];
                a[mt][1] = As[rb + r + 8][k + q];
                a[mt][2] = As[rb + r][k + q + 4];
                a[mt][3] = As[rb + r + 8][k + q + 4];
            }
            uint32_t b[4][2];
#pragma unroll
            for (int nt = 0; nt < 4; nt++) {
                int cb = wn + nt * 8 + r;
                b[nt][0] = Bs[k + q][cb];
                b[nt][1] = Bs[k + q + 4][cb];
            }
#pragma unroll
            for (int mt = 0; mt < 4; mt++)
#pragma unroll
                for (int nt = 0; nt < 4; nt++)
                    mma_tf32(acc[mt][nt], a[mt], b[nt]);
        }
    }

#pragma unroll
    for (int mt = 0; mt < 4; mt++) {
        int row0 = bm + wm + mt * 16 + r;
#pragma unroll
        for (int nt = 0; nt < 4; nt++) {
            int col = bn + wn + nt * 8 + 2 * q;
            float b0 = bias[col], b1 = bias[col + 1];
            float2 o0, o1;
            o0.x = acc[mt][nt][0] + b0; o0.y = acc[mt][nt][1] + b1;
            o1.x = acc[mt][nt][2] + b0; o1.y = acc[mt][nt][3] + b1;
            *(float2*)(C + (size_t)row0 * ldc + col) = o0;
            *(float2*)(C + (size_t)(row0 + 8) * ldc + col) = o1;
        }
    }
}

// ---------------- flash attention (fused scores+softmax+PV) ------------------
// grid (16, 64): x = q-tile (128 rows), y = b*H+h. 256 threads = 8 warps,
// each warp owns 16 q-rows. Streams KV in 64-row chunks with online softmax.
// Dynamic smem: (128*68 + 64*68 + 64*72 + 128*68) * 4 = 105472 bytes.
__global__ __launch_bounds__(256) void flash_kernel(
    const float* __restrict__ qkv, float* __restrict__ attn)
{
    extern __shared__ uint32_t sm[];
    uint32_t (*Qs)[68] = (uint32_t(*)[68])sm;                                      // 128x68
    uint32_t (*Ks)[68] = (uint32_t(*)[68])(sm + 128 * 68);                         // 64x68
    uint32_t (*Vs)[72] = (uint32_t(*)[72])(sm + 128 * 68 + 64 * 68);               // 64x72
    uint32_t (*Ps)[68] = (uint32_t(*)[68])(sm + 128 * 68 + 64 * 68 + 64 * 72);     // 128x68

    int bh = blockIdx.y;
    int b = bh >> 4, h = bh & 15;
    int q0 = blockIdx.x * 128;

    int tid  = threadIdx.x;
    int warp = tid >> 5, lane = tid & 31;
    int q = lane & 3, r = lane >> 2;

    const float* base = qkv + (size_t)b * NSEQ * TD + h * (3 * DH);

    // load Q tile (tf32)
    {
        int row = tid >> 1;
        int c0 = (tid & 1) * 32;
        const float* Qp = base + (size_t)(q0 + row) * TD;
#pragma unroll
        for (int i = 0; i < 8; i++) {
            float4 v = *(const float4*)(Qp + c0 + i * 4);
            Qs[row][c0 + i * 4 + 0] = f2tf(v.x);
            Qs[row][c0 + i * 4 + 1] = f2tf(v.y);
            Qs[row][c0 + i * 4 + 2] = f2tf(v.z);
            Qs[row][c0 + i * 4 + 3] = f2tf(v.w);
        }
    }

    float o[8][4];
#pragma unroll
    for (int nt = 0; nt < 8; nt++)
#pragma unroll
        for (int i = 0; i < 4; i++) o[nt][i] = 0.f;
    float m0 = -1e30f, m1 = -1e30f, l0 = 0.f, l1 = 0.f;

    int kv_row = tid >> 2;             // 0..63
    int kv_c0  = (tid & 3) * 16;       // 0..48

    for (int kt = 0; kt < NSEQ; kt += 64) {
        __syncthreads();               // Qs visible (iter 0) / prior P@V reads done
        const float* Kp = base + (size_t)(kt + kv_row) * TD + DH + kv_c0;
        const float* Vp = base + (size_t)(kt + kv_row) * TD + 2 * DH + kv_c0;
#pragma unroll
        for (int i = 0; i < 4; i++) {
            float4 kv = *(const float4*)(Kp + i * 4);
            Ks[kv_row][kv_c0 + i * 4 + 0] = f2tf(kv.x);
            Ks[kv_row][kv_c0 + i * 4 + 1] = f2tf(kv.y);
            Ks[kv_row][kv_c0 + i * 4 + 2] = f2tf(kv.z);
            Ks[kv_row][kv_c0 + i * 4 + 3] = f2tf(kv.w);
            float4 vv = *(const float4*)(Vp + i * 4);
            Vs[kv_row][kv_c0 + i * 4 + 0] = f2tf(vv.x);
            Vs[kv_row][kv_c0 + i * 4 + 1] = f2tf(vv.y);
            Vs[kv_row][kv_c0 + i * 4 + 2] = f2tf(vv.z);
            Vs[kv_row][kv_c0 + i * 4 + 3] = f2tf(vv.w);
        }
        __syncthreads();

        // S = Q @ K^T (16 q-rows x 64 k-cols per warp)
        float s[8][4];
#pragma unroll
        for (int nt = 0; nt < 8; nt++)
#pragma unroll
            for (int i = 0; i < 4; i++) s[nt][i] = 0.f;

        int rb = warp * 16;
#pragma unroll
        for (int ks = 0; ks < 8; ks++) {
            int k = ks * 8;
            uint32_t a[4];
            a[0] = Qs[rb + r][k + q];
            a[1] = Qs[rb + r + 8][k + q];
            a[2] = Qs[rb + r][k + q + 4];
            a[3] = Qs[rb + r + 8][k + q + 4];
#pragma unroll
            for (int nt = 0; nt < 8; nt++) {
                uint32_t bfr[2];
                bfr[0] = Ks[nt * 8 + r][k + q];
                bfr[1] = Ks[nt * 8 + r][k + q + 4];
                mma_tf32(s[nt], a, bfr);
            }
        }

        // scale + chunk row-max
        float mx0 = -1e30f, mx1 = -1e30f;
#pragma unroll
        for (int nt = 0; nt < 8; nt++) {
            s[nt][0] *= 0.125f; s[nt][1] *= 0.125f;
            s[nt][2] *= 0.125f; s[nt][3] *= 0.125f;
            mx0 = fmaxf(mx0, fmaxf(s[nt][0], s[nt][1]));
            mx1 = fmaxf(mx1, fmaxf(s[nt][2], s[nt][3]));
        }
#pragma unroll
        for (int off = 1; off <= 2; off <<= 1) {
            mx0 = fmaxf(mx0, __shfl_xor_sync(0xffffffffu, mx0, off));
            mx1 = fmaxf(mx1, __shfl_xor_sync(0xffffffffu, mx1, off));
        }

        float mn0 = fmaxf(m0, mx0), mn1 = fmaxf(m1, mx1);
        float al0 = __expf(m0 - mn0), al1 = __expf(m1 - mn1);
        m0 = mn0; m1 = mn1;

        float sum0 = 0.f, sum1 = 0.f;
#pragma unroll
        for (int nt = 0; nt < 8; nt++) {
            float p0 = __expf(s[nt][0] - m0);
            float p1 = __expf(s[nt][1] - m0);
            float p2 = __expf(s[nt][2] - m1);
            float p3 = __expf(s[nt][3] - m1);
            sum0 += p0 + p1; sum1 += p2 + p3;
            int c = nt * 8 + 2 * q;
            Ps[rb + r][c] = f2tf(p0);      Ps[rb + r][c + 1] = f2tf(p1);
            Ps[rb + r + 8][c] = f2tf(p2);  Ps[rb + r + 8][c + 1] = f2tf(p3);
        }
#pragma unroll
        for (int off = 1; off <= 2; off <<= 1) {
            sum0 += __shfl_xor_sync(0xffffffffu, sum0, off);
            sum1 += __shfl_xor_sync(0xffffffffu, sum1, off);
        }
        l0 = l0 * al0 + sum0;
        l1 = l1 * al1 + sum1;

#pragma unroll
        for (int nt = 0; nt < 8; nt++) {
            o[nt][0] *= al0; o[nt][1] *= al0;
            o[nt][2] *= al1; o[nt][3] *= al1;
        }
        __syncwarp();   // Ps rows are warp-private: warp-level sync suffices

        // O += P @ V
#pragma unroll
        for (int ks = 0; ks < 8; ks++) {
            int k = ks * 8;
            uint32_t a[4];
            a[0] = Ps[rb + r][k + q];
            a[1] = Ps[rb + r + 8][k + q];
            a[2] = Ps[rb + r][k + q + 4];
            a[3] = Ps[rb + r + 8][k + q + 4];
#pragma unroll
            for (int nt = 0; nt < 8; nt++) {
                uint32_t bfr[2];
                bfr[0] = Vs[k + q][nt * 8 + r];
                bfr[1] = Vs[k + q + 4][nt * 8 + r];
                mma_tf32(o[nt], a, bfr);
            }
        }
    }

    // normalize, write to [b, n, D]
    float inv0 = 1.f / l0, inv1 = 1.f / l1;
    size_t row0 = (size_t)(b * NSEQ + q0 + warp * 16 + r);
#pragma unroll
    for (int nt = 0; nt < 8; nt++) {
        int col = h * DH + nt * 8 + 2 * q;
        float2 v0, v1;
        v0.x = o[nt][0] * inv0; v0.y = o[nt][1] * inv0;
        v1.x = o[nt][2] * inv1; v1.y = o[nt][3] * inv1;
        *(float2*)(attn + row0 * D + col) = v0;
        *(float2*)(attn + (row0 + 8) * D + col) = v1;
    }
}

// ---------------- launch -----------------------------------------------------
extern "C" void kernel_launch(void* const* d_in, const int* in_sizes, int n_in,
                              void* d_out, int out_size)
{
    const float* z     = (const float*)d_in[0];
    const float* W_qkv = (const float*)d_in[1];
    const float* b_qkv = (const float*)d_in[2];
    const float* W_msa = (const float*)d_in[3];
    const float* b_msa = (const float*)d_in[4];
    float* out = (float*)d_out;

    float *p_qkv = nullptr, *p_attn = nullptr;
    cudaGetSymbolAddress((void**)&p_qkv, g_qkv);
    cudaGetSymbolAddress((void**)&p_attn, g_attn);

    const int fl_smem = (128 * 68 + 64 * 68 + 64 * 72 + 128 * 68) * 4; // 105472
    cudaError_t e = cudaFuncSetAttribute(
        flash_kernel, cudaFuncAttributeMaxDynamicSharedMemorySize, fl_smem);
    (void)e;  // idempotent; checked implicitly by the launch below

    // 1) QKV projection: [8192,1024] @ [1024,3072] + bias
    gemm_tf32<<<dim3(TD / 128, ROWS / 128), 256>>>(
        ROWS, TD, D, z, D, W_qkv, TD, p_qkv, TD, b_qkv);

    // 2) fused flash attention -> [b, n, D]
    flash_kernel<<<dim3(NSEQ / 128, BHN), 256, fl_smem>>>(p_qkv, p_attn);

    // 3) output projection: [8192,1024] @ [1024,1024] + bias
    gemm_tf32<<<dim3(D / 128, ROWS / 128), 256>>>(
        ROWS, D, D, p_attn, D, W_msa, D, out, D, b_msa);
}

// round 4
// speedup vs baseline: 3.3963x; 1.0360x over previous
#include <cuda_runtime.h>
#include <math.h>
#include <stddef.h>
#include <stdint.h>

#define D      1024
#define H      16
#define DH     64
#define NSEQ   2048
#define BATCH  4
#define ROWS   (BATCH*NSEQ)   /* 8192 */
#define BHN    (BATCH*H)      /* 64   */
#define TD     (3*D)          /* 3072 */

// ---------------- scratch ----------------------------------------------------
__device__ float g_qkv[(size_t)ROWS * TD];   // 96 MB
__device__ float g_attn[(size_t)ROWS * D];   // 32 MB

// ---------------- helpers ----------------------------------------------------
__device__ __forceinline__ uint32_t f2tf(float f) {
    uint32_t u;
    asm("cvt.rna.tf32.f32 %0, %1;" : "=r"(u) : "f"(f));
    return u;
}

__device__ __forceinline__ void mma_tf32(float* d, const uint32_t* a, const uint32_t* b) {
    asm volatile(
        "mma.sync.aligned.m16n8k8.row.col.f32.tf32.tf32.f32 "
        "{%0,%1,%2,%3}, {%4,%5,%6,%7}, {%8,%9}, {%0,%1,%2,%3};"
        : "+f"(d[0]), "+f"(d[1]), "+f"(d[2]), "+f"(d[3])
        : "r"(a[0]), "r"(a[1]), "r"(a[2]), "r"(a[3]), "r"(b[0]), "r"(b[1]));
}

__device__ __forceinline__ void cp16(uint32_t dst, const void* src) {
    asm volatile("cp.async.cg.shared.global [%0], [%1], 16;" :: "r"(dst), "l"(src));
}
__device__ __forceinline__ void cp_commit() {
    asm volatile("cp.async.commit_group;" ::: "memory");
}
__device__ __forceinline__ void cp_wait1() {
    asm volatile("cp.async.wait_group 1;" ::: "memory");
}

// ---------------- tf32 GEMM, 3-stage cp.async pipeline -----------------------
// BM=128, BN=128, BK=32, 256 threads = 8 warps (2x4), warp tile 64x32.
// fp32 staged raw in smem; cvt->tf32 on the register load path.
// Dynamic smem: 3 * (128*36 + 32*136) * 4 = 107520 bytes.
#define G_ASZ (128*36)
#define G_BSZ (32*136)
#define G_STG (G_ASZ + G_BSZ)
#define G_SMEM (3 * G_STG * 4)

__global__ __launch_bounds__(256, 2) void gemm_tf32(
    int M, int N, int K,
    const float* __restrict__ A, int lda,
    const float* __restrict__ B, int ldb,
    float* __restrict__ C, int ldc,
    const float* __restrict__ bias)
{
    extern __shared__ float smg[];
    uint32_t smb = (uint32_t)__cvta_generic_to_shared(smg);

    const int BK = 32;
    int tid  = threadIdx.x;
    int warp = tid >> 5, lane = tid & 31;
    int wm   = (warp >> 2) * 64;
    int wn   = (warp & 3) * 32;
    int bm   = blockIdx.y * 128;
    int bn   = blockIdx.x * 128;
    int q    = lane & 3;
    int r    = lane >> 2;

    int arow = tid >> 1;          // 0..127
    int acol = (tid & 1) * 16;    // 0 / 16
    int brow = tid >> 3;          // 0..31
    int bcol = (tid & 7) * 16;    // 0..112

    float acc[4][4][4];
#pragma unroll
    for (int mt = 0; mt < 4; mt++)
#pragma unroll
        for (int nt = 0; nt < 4; nt++)
#pragma unroll
            for (int i = 0; i < 4; i++) acc[mt][nt][i] = 0.f;

    const float* Ab = A + (size_t)(bm + arow) * lda + acol;
    const float* Bb = B + (size_t)brow * ldb + bn + bcol;

    // issue loads for one stage
    auto load_stage = [&](int st, int k0) {
        uint32_t ad = smb + (uint32_t)(st * G_STG + arow * 36 + acol) * 4;
        const float* Ap = Ab + k0;
#pragma unroll
        for (int i = 0; i < 4; i++) cp16(ad + i * 16, Ap + i * 4);
        uint32_t bd = smb + (uint32_t)(st * G_STG + G_ASZ + brow * 136 + bcol) * 4;
        const float* Bp = Bb + (size_t)k0 * ldb;
#pragma unroll
        for (int i = 0; i < 4; i++) cp16(bd + i * 16, Bp + i * 4);
    };

    int NT = K / BK;
    load_stage(0, 0); cp_commit();
    load_stage(1, BK); cp_commit();

    int st = 0;
    for (int it = 0; it < NT; it++) {
        cp_wait1();
        __syncthreads();
        if (it + 2 < NT) load_stage((it + 2) % 3, (it + 2) * BK);
        cp_commit();

        const float* Asf = smg + st * G_STG;
        const float* Bsf = smg + st * G_STG + G_ASZ;

#pragma unroll
        for (int ks = 0; ks < 4; ks++) {
            int k = ks * 8;
            uint32_t a[4][4];
#pragma unroll
            for (int mt = 0; mt < 4; mt++) {
                int rb = wm + mt * 16;
                a[mt][0] = f2tf(Asf[(rb + r) * 36 + k + q]);
                a[mt][1] = f2tf(Asf[(rb + r + 8) * 36 + k + q]);
                a[mt][2] = f2tf(Asf[(rb + r) * 36 + k + q + 4]);
                a[mt][3] = f2tf(Asf[(rb + r + 8) * 36 + k + q + 4]);
            }
            uint32_t b[4][2];
#pragma unroll
            for (int nt = 0; nt < 4; nt++) {
                int cb = wn + nt * 8 + r;
                b[nt][0] = f2tf(Bsf[(k + q) * 136 + cb]);
                b[nt][1] = f2tf(Bsf[(k + q + 4) * 136 + cb]);
            }
#pragma unroll
            for (int mt = 0; mt < 4; mt++)
#pragma unroll
                for (int nt = 0; nt < 4; nt++)
                    mma_tf32(acc[mt][nt], a[mt], b[nt]);
        }
        st = (st + 1) % 3;
        __syncthreads();   // all reads of this stage done before it is re-filled
    }

#pragma unroll
    for (int mt = 0; mt < 4; mt++) {
        int row0 = bm + wm + mt * 16 + r;
#pragma unroll
        for (int nt = 0; nt < 4; nt++) {
            int col = bn + wn + nt * 8 + 2 * q;
            float b0 = bias[col], b1 = bias[col + 1];
            float2 o0, o1;
            o0.x = acc[mt][nt][0] + b0; o0.y = acc[mt][nt][1] + b1;
            o1.x = acc[mt][nt][2] + b0; o1.y = acc[mt][nt][3] + b1;
            *(float2*)(C + (size_t)row0 * ldc + col) = o0;
            *(float2*)(C + (size_t)(row0 + 8) * ldc + col) = o1;
        }
    }
}

// ---------------- flash attention v2 -----------------------------------------
// grid (16, 64), 256 thr = 8 warps, warp = 16 q-rows. Q fragments hoisted to
// registers; Qs smem region reused as Ps. K/V double-buffered with cp.async.
// Dynamic smem floats: QP 128*68 = 8704, per KV stage 64*68 + 64*72 = 8960 x2.
#define F_QP   (128*68)
#define F_KSZ  (64*68)
#define F_STG  (F_KSZ + 64*72)
#define F_KV0  F_QP
#define F_SMEM ((F_QP + 2 * F_STG) * 4)

__global__ __launch_bounds__(256, 2) void flash_kernel(
    const float* __restrict__ qkv, float* __restrict__ attn)
{
    extern __shared__ float smf[];
    uint32_t smb = (uint32_t)__cvta_generic_to_shared(smf);
    uint32_t* QP = (uint32_t*)smf;   // Qs during init, Ps afterwards

    int bh = blockIdx.y;
    int b = bh >> 4, h = bh & 15;
    int q0 = blockIdx.x * 128;

    int tid  = threadIdx.x;
    int warp = tid >> 5, lane = tid & 31;
    int q = lane & 3, r = lane >> 2;
    int rb = warp * 16;

    const float* base = qkv + (size_t)b * NSEQ * TD + h * (3 * DH);

    // ---- load Q tile into QP (as tf32), build fragments, then QP -> Ps ----
    {
        int row = tid >> 1;
        int c0 = (tid & 1) * 32;
        const float* Qp = base + (size_t)(q0 + row) * TD + c0;
#pragma unroll
        for (int i = 0; i < 8; i++) {
            float4 v = *(const float4*)(Qp + i * 4);
            QP[row * 68 + c0 + i * 4 + 0] = f2tf(v.x);
            QP[row * 68 + c0 + i * 4 + 1] = f2tf(v.y);
            QP[row * 68 + c0 + i * 4 + 2] = f2tf(v.z);
            QP[row * 68 + c0 + i * 4 + 3] = f2tf(v.w);
        }
    }

    int kv_row = tid >> 2;             // 0..63
    int kv_c0  = (tid & 3) * 16;       // 0..48

    auto load_kv = [&](int stg, int kt) {
        const float* Kp = base + (size_t)(kt + kv_row) * TD + DH + kv_c0;
        uint32_t kd = smb + (uint32_t)(F_KV0 + stg * F_STG + kv_row * 68 + kv_c0) * 4;
        uint32_t vd = smb + (uint32_t)(F_KV0 + stg * F_STG + F_KSZ + kv_row * 72 + kv_c0) * 4;
#pragma unroll
        for (int i = 0; i < 4; i++) {
            cp16(kd + i * 16, Kp + i * 4);
            cp16(vd + i * 16, Kp + DH + i * 4);
        }
    };

    __syncthreads();                   // Qs written

    uint32_t qf[8][4];
#pragma unroll
    for (int ks = 0; ks < 8; ks++) {
        int k = ks * 8;
        qf[ks][0] = QP[(rb + r) * 68 + k + q];
        qf[ks][1] = QP[(rb + r + 8) * 68 + k + q];
        qf[ks][2] = QP[(rb + r) * 68 + k + q + 4];
        qf[ks][3] = QP[(rb + r + 8) * 68 + k + q + 4];
    }

    load_kv(0, 0);  cp_commit();
    load_kv(1, 64); cp_commit();

    float o[8][4];
#pragma unroll
    for (int nt = 0; nt < 8; nt++)
#pragma unroll
        for (int i = 0; i < 4; i++) o[nt][i] = 0.f;
    float m0 = -1e30f, m1 = -1e30f, l0 = 0.f, l1 = 0.f;

    __syncthreads();                   // Q frags built; QP now reusable as Ps

    for (int c = 0; c < NSEQ / 64; c++) {
        cp_wait1();
        __syncthreads();               // stage c%2 ready; prev compute done

        const float* Ksf = smf + F_KV0 + (c & 1) * F_STG;
        const float* Vsf = Ksf + F_KSZ;

        // S = Q @ K^T
        float s[8][4];
#pragma unroll
        for (int nt = 0; nt < 8; nt++)
#pragma unroll
            for (int i = 0; i < 4; i++) s[nt][i] = 0.f;

#pragma unroll
        for (int ks = 0; ks < 8; ks++) {
            int k = ks * 8;
#pragma unroll
            for (int nt = 0; nt < 8; nt++) {
                uint32_t bfr[2];
                bfr[0] = f2tf(Ksf[(nt * 8 + r) * 68 + k + q]);
                bfr[1] = f2tf(Ksf[(nt * 8 + r) * 68 + k + q + 4]);
                mma_tf32(s[nt], qf[ks], bfr);
            }
        }

        // online softmax
        float mx0 = -1e30f, mx1 = -1e30f;
#pragma unroll
        for (int nt = 0; nt < 8; nt++) {
            s[nt][0] *= 0.125f; s[nt][1] *= 0.125f;
            s[nt][2] *= 0.125f; s[nt][3] *= 0.125f;
            mx0 = fmaxf(mx0, fmaxf(s[nt][0], s[nt][1]));
            mx1 = fmaxf(mx1, fmaxf(s[nt][2], s[nt][3]));
        }
#pragma unroll
        for (int off = 1; off <= 2; off <<= 1) {
            mx0 = fmaxf(mx0, __shfl_xor_sync(0xffffffffu, mx0, off));
            mx1 = fmaxf(mx1, __shfl_xor_sync(0xffffffffu, mx1, off));
        }
        float mn0 = fmaxf(m0, mx0), mn1 = fmaxf(m1, mx1);
        float al0 = __expf(m0 - mn0), al1 = __expf(m1 - mn1);
        m0 = mn0; m1 = mn1;

        float sum0 = 0.f, sum1 = 0.f;
#pragma unroll
        for (int nt = 0; nt < 8; nt++) {
            float p0 = __expf(s[nt][0] - m0);
            float p1 = __expf(s[nt][1] - m0);
            float p2 = __expf(s[nt][2] - m1);
            float p3 = __expf(s[nt][3] - m1);
            sum0 += p0 + p1; sum1 += p2 + p3;
            int cc = nt * 8 + 2 * q;
            QP[(rb + r) * 68 + cc]     = f2tf(p0);
            QP[(rb + r) * 68 + cc + 1] = f2tf(p1);
            QP[(rb + r + 8) * 68 + cc]     = f2tf(p2);
            QP[(rb + r + 8) * 68 + cc + 1] = f2tf(p3);
        }
#pragma unroll
        for (int off = 1; off <= 2; off <<= 1) {
            sum0 += __shfl_xor_sync(0xffffffffu, sum0, off);
            sum1 += __shfl_xor_sync(0xffffffffu, sum1, off);
        }
        l0 = l0 * al0 + sum0;
        l1 = l1 * al1 + sum1;

#pragma unroll
        for (int nt = 0; nt < 8; nt++) {
            o[nt][0] *= al0; o[nt][1] *= al0;
            o[nt][2] *= al1; o[nt][3] *= al1;
        }
        __syncwarp();                  // Ps rows are warp-private

        // O += P @ V
#pragma unroll
        for (int ks = 0; ks < 8; ks++) {
            int k = ks * 8;
            uint32_t a[4];
            a[0] = QP[(rb + r) * 68 + k + q];
            a[1] = QP[(rb + r + 8) * 68 + k + q];
            a[2] = QP[(rb + r) * 68 + k + q + 4];
            a[3] = QP[(rb + r + 8) * 68 + k + q + 4];
#pragma unroll
            for (int nt = 0; nt < 8; nt++) {
                uint32_t bfr[2];
                bfr[0] = f2tf(Vsf[(k + q) * 72 + nt * 8 + r]);
                bfr[1] = f2tf(Vsf[(k + q + 4) * 72 + nt * 8 + r]);
                mma_tf32(o[nt], a, bfr);
            }
        }

        __syncthreads();               // all reads of stage c%2 done
        if (c + 2 < NSEQ / 64) load_kv(c & 1, (c + 2) * 64);
        cp_commit();
    }

    // normalize, write to [b, n, D]
    float inv0 = 1.f / l0, inv1 = 1.f / l1;
    size_t row0 = (size_t)(b * NSEQ + q0 + rb + r);
#pragma unroll
    for (int nt = 0; nt < 8; nt++) {
        int col = h * DH + nt * 8 + 2 * q;
        float2 v0, v1;
        v0.x = o[nt][0] * inv0; v0.y = o[nt][1] * inv0;
        v1.x = o[nt][2] * inv1; v1.y = o[nt][3] * inv1;
        *(float2*)(attn + row0 * D + col) = v0;
        *(float2*)(attn + (row0 + 8) * D + col) = v1;
    }
}

// ---------------- launch -----------------------------------------------------
extern "C" void kernel_launch(void* const* d_in, const int* in_sizes, int n_in,
                              void* d_out, int out_size)
{
    const float* z     = (const float*)d_in[0];
    const float* W_qkv = (const float*)d_in[1];
    const float* b_qkv = (const float*)d_in[2];
    const float* W_msa = (const float*)d_in[3];
    const float* b_msa = (const float*)d_in[4];
    float* out = (float*)d_out;

    float *p_qkv = nullptr, *p_attn = nullptr;
    cudaGetSymbolAddress((void**)&p_qkv, g_qkv);
    cudaGetSymbolAddress((void**)&p_attn, g_attn);

    cudaFuncSetAttribute(gemm_tf32,
                         cudaFuncAttributeMaxDynamicSharedMemorySize, G_SMEM);
    cudaFuncSetAttribute(flash_kernel,
                         cudaFuncAttributeMaxDynamicSharedMemorySize, F_SMEM);

    // 1) QKV projection: [8192,1024] @ [1024,3072] + bias
    gemm_tf32<<<dim3(TD / 128, ROWS / 128), 256, G_SMEM>>>(
        ROWS, TD, D, z, D, W_qkv, TD, p_qkv, TD, b_qkv);

    // 2) fused flash attention -> [b, n, D]
    flash_kernel<<<dim3(NSEQ / 128, BHN), 256, F_SMEM>>>(p_qkv, p_attn);

    // 3) output projection: [8192,1024] @ [1024,1024] + bias
    gemm_tf32<<<dim3(D / 128, ROWS / 128), 256, G_SMEM>>>(
        ROWS, D, D, p_attn, D, W_msa, D, out, D, b_msa);
}

// round 7
// speedup vs baseline: 3.6532x; 1.0756x over previous
#include <cuda_runtime.h>
#include <math.h>
#include <stddef.h>
#include <stdint.h>

#define D      1024
#define H      16
#define DH     64
#define NSEQ   2048
#define BATCH  4
#define ROWS   (BATCH*NSEQ)   /* 8192 */
#define BHN    (BATCH*H)      /* 64   */
#define TD     (3*D)          /* 3072 */

// ---------------- scratch ----------------------------------------------------
__device__ float g_qkv[(size_t)ROWS * TD];   // 96 MB (tf32-rounded at epilogue)
__device__ float g_attn[(size_t)ROWS * D];   // 32 MB (tf32-rounded at epilogue)
__device__ float g_z [(size_t)ROWS * D];     // 32 MB rounded z
__device__ float g_wq[(size_t)D * TD];       // 12 MB rounded W_qkv
__device__ float g_wm[(size_t)D * D];        //  4 MB rounded W_msa

// ---------------- helpers ----------------------------------------------------
__device__ __forceinline__ uint32_t f2tf(float f) {
    uint32_t u;
    asm("cvt.rna.tf32.f32 %0, %1;" : "=r"(u) : "f"(f));
    return u;
}
__device__ __forceinline__ float f2tff(float f) { return __uint_as_float(f2tf(f)); }

// operands in memory are pre-rounded to tf32 (RNA): MMA consumes raw bits.
__device__ __forceinline__ void mma_tf32(float* d, const uint32_t* a, const uint32_t* b) {
    asm volatile(
        "mma.sync.aligned.m16n8k8.row.col.f32.tf32.tf32.f32 "
        "{%0,%1,%2,%3}, {%4,%5,%6,%7}, {%8,%9}, {%0,%1,%2,%3};"
        : "+f"(d[0]), "+f"(d[1]), "+f"(d[2]), "+f"(d[3])
        : "r"(a[0]), "r"(a[1]), "r"(a[2]), "r"(a[3]), "r"(b[0]), "r"(b[1]));
}

__device__ __forceinline__ void cp16(uint32_t dst, const void* src) {
    asm volatile("cp.async.cg.shared.global [%0], [%1], 16;" :: "r"(dst), "l"(src));
}
__device__ __forceinline__ void cp_commit() {
    asm volatile("cp.async.commit_group;" ::: "memory");
}
__device__ __forceinline__ void cp_wait1() {
    asm volatile("cp.async.wait_group 1;" ::: "memory");
}

// ---------------- prep: elementwise RNA round to tf32 ------------------------
__global__ __launch_bounds__(256) void round_kernel(
    const float* __restrict__ in, float* __restrict__ out, int n4)
{
    int i = blockIdx.x * 256 + threadIdx.x;
    if (i < n4) {
        float4 v = ((const float4*)in)[i];
        v.x = f2tff(v.x); v.y = f2tff(v.y);
        v.z = f2tff(v.z); v.w = f2tff(v.w);
        ((float4*)out)[i] = v;
    }
}

// ---------------- tf32 GEMM, 3-stage cp.async pipeline -----------------------
// BM=128, BN=128, BK=32, 256 threads = 8 warps (2x4), warp tile 64x32.
// Operands pre-rounded in gmem; zero CVTs in the mainloop.
#define G_ASZ (128*36)
#define G_BSZ (32*136)
#define G_STG (G_ASZ + G_BSZ)
#define G_SMEM (3 * G_STG * 4)

__global__ __launch_bounds__(256, 2) void gemm_tf32(
    int M, int N, int K,
    const float* __restrict__ A, int lda,
    const float* __restrict__ B, int ldb,
    float* __restrict__ C, int ldc,
    const float* __restrict__ bias,
    int round_out)
{
    extern __shared__ float smg[];
    uint32_t smb = (uint32_t)__cvta_generic_to_shared(smg);

    const int BK = 32;
    int tid  = threadIdx.x;
    int warp = tid >> 5, lane = tid & 31;
    int wm   = (warp >> 2) * 64;
    int wn   = (warp & 3) * 32;
    int bm   = blockIdx.y * 128;
    int bn   = blockIdx.x * 128;
    int q    = lane & 3;
    int r    = lane >> 2;

    int arow = tid >> 1;          // 0..127
    int acol = (tid & 1) * 16;    // 0 / 16
    int brow = tid >> 3;          // 0..31
    int bcol = (tid & 7) * 16;    // 0..112

    float acc[4][4][4];
#pragma unroll
    for (int mt = 0; mt < 4; mt++)
#pragma unroll
        for (int nt = 0; nt < 4; nt++)
#pragma unroll
            for (int i = 0; i < 4; i++) acc[mt][nt][i] = 0.f;

    const float* Ab = A + (size_t)(bm + arow) * lda + acol;
    const float* Bb = B + (size_t)brow * ldb + bn + bcol;

    auto load_stage = [&](int st, int k0) {
        uint32_t ad = smb + (uint32_t)(st * G_STG + arow * 36 + acol) * 4;
        const float* Ap = Ab + k0;
#pragma unroll
        for (int i = 0; i < 4; i++) cp16(ad + i * 16, Ap + i * 4);
        uint32_t bd = smb + (uint32_t)(st * G_STG + G_ASZ + brow * 136 + bcol) * 4;
        const float* Bp = Bb + (size_t)k0 * ldb;
#pragma unroll
        for (int i = 0; i < 4; i++) cp16(bd + i * 16, Bp + i * 4);
    };

    int NT = K / BK;
    load_stage(0, 0); cp_commit();
    load_stage(1, BK); cp_commit();

    int st = 0;
    for (int it = 0; it < NT; it++) {
        cp_wait1();
        __syncthreads();   // stage st ready; stage (it+2)%3 was consumed at it-1
        if (it + 2 < NT) load_stage((it + 2) % 3, (it + 2) * BK);
        cp_commit();

        const uint32_t* Asu = (const uint32_t*)(smg + st * G_STG);
        const uint32_t* Bsu = (const uint32_t*)(smg + st * G_STG + G_ASZ);

#pragma unroll
        for (int ks = 0; ks < 4; ks++) {
            int k = ks * 8;
            uint32_t a[4][4];
#pragma unroll
            for (int mt = 0; mt < 4; mt++) {
                int rb = wm + mt * 16;
                a[mt][0] = Asu[(rb + r) * 36 + k + q];
                a[mt][1] = Asu[(rb + r + 8) * 36 + k + q];
                a[mt][2] = Asu[(rb + r) * 36 + k + q + 4];
                a[mt][3] = Asu[(rb + r + 8) * 36 + k + q + 4];
            }
            uint32_t b[4][2];
#pragma unroll
            for (int nt = 0; nt < 4; nt++) {
                int cb = wn + nt * 8 + r;
                b[nt][0] = Bsu[(k + q) * 136 + cb];
                b[nt][1] = Bsu[(k + q + 4) * 136 + cb];
            }
#pragma unroll
            for (int mt = 0; mt < 4; mt++)
#pragma unroll
                for (int nt = 0; nt < 4; nt++)
                    mma_tf32(acc[mt][nt], a[mt], b[nt]);
        }
        st = (st + 1) % 3;
    }

#pragma unroll
    for (int mt = 0; mt < 4; mt++) {
        int row0 = bm + wm + mt * 16 + r;
#pragma unroll
        for (int nt = 0; nt < 4; nt++) {
            int col = bn + wn + nt * 8 + 2 * q;
            float b0 = bias[col], b1 = bias[col + 1];
            float2 o0, o1;
            o0.x = acc[mt][nt][0] + b0; o0.y = acc[mt][nt][1] + b1;
            o1.x = acc[mt][nt][2] + b0; o1.y = acc[mt][nt][3] + b1;
            if (round_out) {   // output feeds a later MMA: pre-round to tf32
                o0.x = f2tff(o0.x); o0.y = f2tff(o0.y);
                o1.x = f2tff(o1.x); o1.y = f2tff(o1.y);
            }
            *(float2*)(C + (size_t)row0 * ldc + col) = o0;
            *(float2*)(C + (size_t)(row0 + 8) * ldc + col) = o1;
        }
    }
}

// ---------------- flash attention --------------------------------------------
// grid (16, 64), 256 thr = 8 warps, warp = 16 q-rows. Q fragments in registers
// (pre-scaled by 1/8 — exact pow2 on tf32-rounded data); Qs smem reused as Ps.
// K/V double-buffered via cp.async. All MMA operands tf32-rounded in memory.
#define F_QP   (128*68)
#define F_KSZ  (64*68)
#define F_STG  (F_KSZ + 64*72)
#define F_KV0  F_QP
#define F_SMEM ((F_QP + 2 * F_STG) * 4)

__global__ __launch_bounds__(256, 2) void flash_kernel(
    const float* __restrict__ qkv, float* __restrict__ attn)
{
    extern __shared__ float smf[];
    uint32_t smb = (uint32_t)__cvta_generic_to_shared(smf);
    uint32_t* QP = (uint32_t*)smf;   // Qs during init, Ps afterwards

    int bh = blockIdx.y;
    int b = bh >> 4, h = bh & 15;
    int q0 = blockIdx.x * 128;

    int tid  = threadIdx.x;
    int warp = tid >> 5, lane = tid & 31;
    int q = lane & 3, r = lane >> 2;
    int rb = warp * 16;

    const float* base = qkv + (size_t)b * NSEQ * TD + h * (3 * DH);

    // ---- load Q tile (x0.125 exact; data already tf32-rounded) ----
    {
        int row = tid >> 1;
        int c0 = (tid & 1) * 32;
        const float* Qp = base + (size_t)(q0 + row) * TD + c0;
#pragma unroll
        for (int i = 0; i < 8; i++) {
            float4 v = *(const float4*)(Qp + i * 4);
            QP[row * 68 + c0 + i * 4 + 0] = __float_as_uint(v.x * 0.125f);
            QP[row * 68 + c0 + i * 4 + 1] = __float_as_uint(v.y * 0.125f);
            QP[row * 68 + c0 + i * 4 + 2] = __float_as_uint(v.z * 0.125f);
            QP[row * 68 + c0 + i * 4 + 3] = __float_as_uint(v.w * 0.125f);
        }
    }

    int kv_row = tid >> 2;             // 0..63
    int kv_c0  = (tid & 3) * 16;       // 0..48

    auto load_kv = [&](int stg, int kt) {
        const float* Kp = base + (size_t)(kt + kv_row) * TD + DH + kv_c0;
        uint32_t kd = smb + (uint32_t)(F_KV0 + stg * F_STG + kv_row * 68 + kv_c0) * 4;
        uint32_t vd = smb + (uint32_t)(F_KV0 + stg * F_STG + F_KSZ + kv_row * 72 + kv_c0) * 4;
#pragma unroll
        for (int i = 0; i < 4; i++) {
            cp16(kd + i * 16, Kp + i * 4);
            cp16(vd + i * 16, Kp + DH + i * 4);
        }
    };

    __syncthreads();                   // Qs written

    uint32_t qf[8][4];
#pragma unroll
    for (int ks = 0; ks < 8; ks++) {
        int k = ks * 8;
        qf[ks][0] = QP[(rb + r) * 68 + k + q];
        qf[ks][1] = QP[(rb + r + 8) * 68 + k + q];
        qf[ks][2] = QP[(rb + r) * 68 + k + q + 4];
        qf[ks][3] = QP[(rb + r + 8) * 68 + k + q + 4];
    }

    load_kv(0, 0);  cp_commit();
    load_kv(1, 64); cp_commit();

    float o[8][4];
#pragma unroll
    for (int nt = 0; nt < 8; nt++)
#pragma unroll
        for (int i = 0; i < 4; i++) o[nt][i] = 0.f;
    float m0 = -1e30f, m1 = -1e30f, l0 = 0.f, l1 = 0.f;

    __syncthreads();                   // Q frags built; QP reusable as Ps

    for (int c = 0; c < NSEQ / 64; c++) {
        cp_wait1();
        __syncthreads();               // stage c%2 ready

        const uint32_t* Ksu = (const uint32_t*)(smf + F_KV0 + (c & 1) * F_STG);
        const uint32_t* Vsu = Ksu + F_KSZ;

        // S = (Q/8) @ K^T
        float s[8][4];
#pragma unroll
        for (int nt = 0; nt < 8; nt++)
#pragma unroll
            for (int i = 0; i < 4; i++) s[nt][i] = 0.f;

#pragma unroll
        for (int ks = 0; ks < 8; ks++) {
            int k = ks * 8;
#pragma unroll
            for (int nt = 0; nt < 8; nt++) {
                uint32_t bfr[2];
                bfr[0] = Ksu[(nt * 8 + r) * 68 + k + q];
                bfr[1] = Ksu[(nt * 8 + r) * 68 + k + q + 4];
                mma_tf32(s[nt], qf[ks], bfr);
            }
        }

        // online softmax
        float mx0 = -1e30f, mx1 = -1e30f;
#pragma unroll
        for (int nt = 0; nt < 8; nt++) {
            mx0 = fmaxf(mx0, fmaxf(s[nt][0], s[nt][1]));
            mx1 = fmaxf(mx1, fmaxf(s[nt][2], s[nt][3]));
        }
#pragma unroll
        for (int off = 1; off <= 2; off <<= 1) {
            mx0 = fmaxf(mx0, __shfl_xor_sync(0xffffffffu, mx0, off));
            mx1 = fmaxf(mx1, __shfl_xor_sync(0xffffffffu, mx1, off));
        }
        float mn0 = fmaxf(m0, mx0), mn1 = fmaxf(m1, mx1);
        float al0 = __expf(m0 - mn0), al1 = __expf(m1 - mn1);
        m0 = mn0; m1 = mn1;

        float sum0 = 0.f, sum1 = 0.f;
#pragma unroll
        for (int nt = 0; nt < 8; nt++) {
            float p0 = __expf(s[nt][0] - m0);
            float p1 = __expf(s[nt][1] - m0);
            float p2 = __expf(s[nt][2] - m1);
            float p3 = __expf(s[nt][3] - m1);
            sum0 += p0 + p1; sum1 += p2 + p3;
            int cc = nt * 8 + 2 * q;
            QP[(rb + r) * 68 + cc]         = f2tf(p0);   // RNA-round P
            QP[(rb + r) * 68 + cc + 1]     = f2tf(p1);
            QP[(rb + r + 8) * 68 + cc]     = f2tf(p2);
            QP[(rb + r + 8) * 68 + cc + 1] = f2tf(p3);
        }
#pragma unroll
        for (int off = 1; off <= 2; off <<= 1) {
            sum0 += __shfl_xor_sync(0xffffffffu, sum0, off);
            sum1 += __shfl_xor_sync(0xffffffffu, sum1, off);
        }
        l0 = l0 * al0 + sum0;
        l1 = l1 * al1 + sum1;

#pragma unroll
        for (int nt = 0; nt < 8; nt++) {
            o[nt][0] *= al0; o[nt][1] *= al0;
            o[nt][2] *= al1; o[nt][3] *= al1;
        }
        __syncwarp();                  // Ps rows are warp-private

        // O += P @ V
#pragma unroll
        for (int ks = 0; ks < 8; ks++) {
            int k = ks * 8;
            uint32_t a[4];
            a[0] = QP[(rb + r) * 68 + k + q];
            a[1] = QP[(rb + r + 8) * 68 + k + q];
            a[2] = QP[(rb + r) * 68 + k + q + 4];
            a[3] = QP[(rb + r + 8) * 68 + k + q + 4];
#pragma unroll
            for (int nt = 0; nt < 8; nt++) {
                uint32_t bfr[2];
                bfr[0] = Vsu[(k + q) * 72 + nt * 8 + r];
                bfr[1] = Vsu[(k + q + 4) * 72 + nt * 8 + r];
                mma_tf32(o[nt], a, bfr);
            }
        }

        __syncthreads();               // stage c%2 fully consumed
        if (c + 2 < NSEQ / 64) load_kv(c & 1, (c + 2) * 64);
        cp_commit();
    }

    // normalize, round (feeds out-proj MMA), write to [b, n, D]
    float inv0 = 1.f / l0, inv1 = 1.f / l1;
    size_t row0 = (size_t)(b * NSEQ + q0 + rb + r);
#pragma unroll
    for (int nt = 0; nt < 8; nt++) {
        int col = h * DH + nt * 8 + 2 * q;
        float2 v0, v1;
        v0.x = f2tff(o[nt][0] * inv0); v0.y = f2tff(o[nt][1] * inv0);
        v1.x = f2tff(o[nt][2] * inv1); v1.y = f2tff(o[nt][3] * inv1);
        *(float2*)(attn + row0 * D + col) = v0;
        *(float2*)(attn + (row0 + 8) * D + col) = v1;
    }
}

// ---------------- launch -----------------------------------------------------
extern "C" void kernel_launch(void* const* d_in, const int* in_sizes, int n_in,
                              void* d_out, int out_size)
{
    const float* z     = (const float*)d_in[0];
    const float* W_qkv = (const float*)d_in[1];
    const float* b_qkv = (const float*)d_in[2];
    const float* W_msa = (const float*)d_in[3];
    const float* b_msa = (const float*)d_in[4];
    float* out = (float*)d_out;

    float *p_qkv, *p_attn, *p_z, *p_wq, *p_wm;
    cudaGetSymbolAddress((void**)&p_qkv, g_qkv);
    cudaGetSymbolAddress((void**)&p_attn, g_attn);
    cudaGetSymbolAddress((void**)&p_z, g_z);
    cudaGetSymbolAddress((void**)&p_wq, g_wq);
    cudaGetSymbolAddress((void**)&p_wm, g_wm);

    cudaFuncSetAttribute(gemm_tf32,
                         cudaFuncAttributeMaxDynamicSharedMemorySize, G_SMEM);
    cudaFuncSetAttribute(flash_kernel,
                         cudaFuncAttributeMaxDynamicSharedMemorySize, F_SMEM);

    // 0) pre-round operands to tf32 (RNA)
    {
        int n4z = ROWS * D / 4, n4q = D * TD / 4, n4m = D * D / 4;
        round_kernel<<<(n4z + 255) / 256, 256>>>(z, p_z, n4z);
        round_kernel<<<(n4q + 255) / 256, 256>>>(W_qkv, p_wq, n4q);
        round_kernel<<<(n4m + 255) / 256, 256>>>(W_msa, p_wm, n4m);
    }

    // 1) QKV projection (output rounded: feeds flash MMAs)
    gemm_tf32<<<dim3(TD / 128, ROWS / 128), 256, G_SMEM>>>(
        ROWS, TD, D, p_z, D, p_wq, TD, p_qkv, TD, b_qkv, 1);

    // 2) fused flash attention -> [b, n, D] (output rounded: feeds out-proj)
    flash_kernel<<<dim3(NSEQ / 128, BHN), 256, F_SMEM>>>(p_qkv, p_attn);

    // 3) output projection (final output: NOT rounded)
    gemm_tf32<<<dim3(D / 128, ROWS / 128), 256, G_SMEM>>>(
        ROWS, D, D, p_attn, D, p_wm, D, out, D, b_msa, 0);
}

// round 8
// speedup vs baseline: 3.9709x; 1.0870x over previous
#include <cuda_runtime.h>
#include <math.h>
#include <stddef.h>
#include <stdint.h>

#define D      1024
#define H      16
#define DH     64
#define NSEQ   2048
#define BATCH  4
#define ROWS   (BATCH*NSEQ)   /* 8192 */
#define BHN    (BATCH*H)      /* 64   */
#define TD     (3*D)          /* 3072 */

// ---------------- scratch ----------------------------------------------------
__device__ float g_qkv[(size_t)ROWS * TD];        // 96 MB (tf32-rounded)
__device__ float g_attn[(size_t)ROWS * D];        // 32 MB (tf32-rounded)
__device__ float g_z  [(size_t)ROWS * D];         // 32 MB rounded z
__device__ float g_wq [(size_t)TD * D];           // 12 MB rounded W_qkv^T  [n][k]
__device__ float g_wm [(size_t)D * D];            //  4 MB rounded W_msa^T  [n][k]
__device__ float g_vT [(size_t)BHN * DH * NSEQ];  // 33.5 MB V transposed [bh][dh][tok]

// ---------------- helpers ----------------------------------------------------
__device__ __forceinline__ uint32_t f2tf(float f) {
    uint32_t u;
    asm("cvt.rna.tf32.f32 %0, %1;" : "=r"(u) : "f"(f));
    return u;
}
__device__ __forceinline__ float f2tff(float f) { return __uint_as_float(f2tf(f)); }

__device__ __forceinline__ void mma_tf32(float* d, const uint32_t* a, const uint32_t* b) {
    asm volatile(
        "mma.sync.aligned.m16n8k8.row.col.f32.tf32.tf32.f32 "
        "{%0,%1,%2,%3}, {%4,%5,%6,%7}, {%8,%9}, {%0,%1,%2,%3};"
        : "+f"(d[0]), "+f"(d[1]), "+f"(d[2]), "+f"(d[3])
        : "r"(a[0]), "r"(a[1]), "r"(a[2]), "r"(a[3]), "r"(b[0]), "r"(b[1]));
}

// ldmatrix on 32-bit data: each 8x8 b16 matrix == 8x4 b32 tile with thread
// (r=lane>>2, q=lane&3) ownership — exactly the tf32 mma fragment layout.
__device__ __forceinline__ void ldsm4(uint32_t* d, uint32_t addr) {
    asm volatile("ldmatrix.sync.aligned.m8n8.x4.shared.b16 {%0,%1,%2,%3}, [%4];"
        : "=r"(d[0]), "=r"(d[1]), "=r"(d[2]), "=r"(d[3]) : "r"(addr));
}
__device__ __forceinline__ void ldsm2(uint32_t* d, uint32_t addr) {
    asm volatile("ldmatrix.sync.aligned.m8n8.x2.shared.b16 {%0,%1}, [%2];"
        : "=r"(d[0]), "=r"(d[1]) : "r"(addr));
}

__device__ __forceinline__ void cp16(uint32_t dst, const void* src) {
    asm volatile("cp.async.cg.shared.global [%0], [%1], 16;" :: "r"(dst), "l"(src));
}
__device__ __forceinline__ void cp_commit() {
    asm volatile("cp.async.commit_group;" ::: "memory");
}
__device__ __forceinline__ void cp_wait1() {
    asm volatile("cp.async.wait_group 1;" ::: "memory");
}

// ---------------- prep kernels -----------------------------------------------
__global__ __launch_bounds__(256) void round_kernel(
    const float* __restrict__ in, float* __restrict__ out, int n4)
{
    int i = blockIdx.x * 256 + threadIdx.x;
    if (i < n4) {
        float4 v = ((const float4*)in)[i];
        v.x = f2tff(v.x); v.y = f2tff(v.y);
        v.z = f2tff(v.z); v.w = f2tff(v.w);
        ((float4*)out)[i] = v;
    }
}

// Wt[n][k] = round(W[k][n]); W is [Kd][Nd] row-major. block (32,8)
__global__ __launch_bounds__(256) void trw_kernel(
    const float* __restrict__ W, float* __restrict__ Wt, int Kd, int Nd)
{
    __shared__ float t[32][33];
    int k0 = blockIdx.x * 32, n0 = blockIdx.y * 32;
    int tx = threadIdx.x, ty = threadIdx.y;
#pragma unroll
    for (int i = 0; i < 4; i++)
        t[ty + i * 8][tx] = W[(size_t)(k0 + ty + i * 8) * Nd + n0 + tx];
    __syncthreads();
#pragma unroll
    for (int i = 0; i < 4; i++)
        Wt[(size_t)(n0 + ty + i * 8) * Kd + k0 + tx] = f2tff(t[tx][ty + i * 8]);
}

// vT[bh][dh][tok] = qkv[b, tok, h*192 + 128 + dh]  (values already rounded)
__global__ __launch_bounds__(256) void vT_kernel(const float* __restrict__ qkv,
                                                 float* __restrict__ vT)
{
    __shared__ float t[32][33];
    int bh = blockIdx.y >> 1;
    int dh0 = (blockIdx.y & 1) * 32;
    int t0 = blockIdx.x * 32;
    int b = bh >> 4, h = bh & 15;
    int tx = threadIdx.x, ty = threadIdx.y;
#pragma unroll
    for (int i = 0; i < 4; i++)
        t[ty + i * 8][tx] =
            qkv[(size_t)(b * NSEQ + t0 + ty + i * 8) * TD + h * (3 * DH) + 2 * DH + dh0 + tx];
    __syncthreads();
#pragma unroll
    for (int i = 0; i < 4; i++)
        vT[((size_t)bh * DH + dh0 + ty + i * 8) * NSEQ + t0 + tx] = t[tx][ty + i * 8];
}

// ---------------- tf32 GEMM, 3-stage cp.async + ldmatrix ---------------------
// BM=128, BN=128, BK=32, 256 threads = 8 warps (2x4), warp tile 64x32.
// A [m][k] row-major, Bt [n][k] row-major; both LDSM-native. Stride 36 words
// (144 B) => row chunks tile all 32 banks: conflict-free LDSM.
#define G_ASZ (128*36)
#define G_STG (2*G_ASZ)
#define G_SMEM (3 * G_STG * 4)

__global__ __launch_bounds__(256, 2) void gemm_tf32(
    int M, int N, int K,
    const float* __restrict__ A, int lda,
    const float* __restrict__ Bt, int ldb,
    float* __restrict__ C, int ldc,
    const float* __restrict__ bias,
    int round_out)
{
    extern __shared__ float smg[];
    uint32_t smb = (uint32_t)__cvta_generic_to_shared(smg);

    const int BK = 32;
    int tid  = threadIdx.x;
    int warp = tid >> 5, lane = tid & 31;
    int wm   = (warp >> 2) * 64;
    int wn   = (warp & 3) * 32;
    int bm   = blockIdx.y * 128;
    int bn   = blockIdx.x * 128;
    int q    = lane & 3;
    int r    = lane >> 2;
    int lane8 = lane & 7, gq = lane >> 3;

    int srow = tid >> 1;          // 0..127 staging row (A and B)
    int scol = (tid & 1) * 16;    // 0 / 16

    float acc[4][4][4];
#pragma unroll
    for (int mt = 0; mt < 4; mt++)
#pragma unroll
        for (int nt = 0; nt < 4; nt++)
#pragma unroll
            for (int i = 0; i < 4; i++) acc[mt][nt][i] = 0.f;

    const float* Ab = A  + (size_t)(bm + srow) * lda + scol;
    const float* Bb = Bt + (size_t)(bn + srow) * ldb + scol;

    auto load_stage = [&](int st, int k0) {
        uint32_t ad = smb + (uint32_t)(st * G_STG + srow * 36 + scol) * 4;
        uint32_t bd = ad + (uint32_t)G_ASZ * 4;
#pragma unroll
        for (int i = 0; i < 4; i++) {
            cp16(ad + i * 16, Ab + k0 + i * 4);
            cp16(bd + i * 16, Bb + k0 + i * 4);
        }
    };

    // per-thread ldmatrix address components
    uint32_t a_row = wm + lane8 + 8 * (gq & 1);
    uint32_t a_col = 4 * (gq >> 1);
    uint32_t b_row = wn + (gq >> 1) * 8 + lane8;
    uint32_t b_col = 4 * (gq & 1);

    int NT = K / BK;
    load_stage(0, 0); cp_commit();
    load_stage(1, BK); cp_commit();

    int st = 0;
    for (int it = 0; it < NT; it++) {
        cp_wait1();
        __syncthreads();
        if (it + 2 < NT) load_stage((it + 2) % 3, (it + 2) * BK);
        cp_commit();

        uint32_t abase = smb + (uint32_t)(st * G_STG) * 4;
        uint32_t bbase = abase + (uint32_t)G_ASZ * 4;

#pragma unroll
        for (int ks = 0; ks < 4; ks++) {
            uint32_t a[4][4];
#pragma unroll
            for (int mt = 0; mt < 4; mt++)
                ldsm4(a[mt], abase + ((a_row + mt * 16) * 36 + ks * 8 + a_col) * 4);
            uint32_t bb[2][4];
#pragma unroll
            for (int ntp = 0; ntp < 2; ntp++)
                ldsm4(bb[ntp], bbase + ((b_row + ntp * 16) * 36 + ks * 8 + b_col) * 4);
#pragma unroll
            for (int mt = 0; mt < 4; mt++)
#pragma unroll
                for (int nt = 0; nt < 4; nt++)
                    mma_tf32(acc[mt][nt], a[mt], &bb[nt >> 1][(nt & 1) * 2]);
        }
        st = (st + 1) % 3;
    }

#pragma unroll
    for (int mt = 0; mt < 4; mt++) {
        int row0 = bm + wm + mt * 16 + r;
#pragma unroll
        for (int nt = 0; nt < 4; nt++) {
            int col = bn + wn + nt * 8 + 2 * q;
            float b0 = bias[col], b1 = bias[col + 1];
            float2 o0, o1;
            o0.x = acc[mt][nt][0] + b0; o0.y = acc[mt][nt][1] + b1;
            o1.x = acc[mt][nt][2] + b0; o1.y = acc[mt][nt][3] + b1;
            if (round_out) {
                o0.x = f2tff(o0.x); o0.y = f2tff(o0.y);
                o1.x = f2tff(o1.x); o1.y = f2tff(o1.y);
            }
            *(float2*)(C + (size_t)row0 * ldc + col) = o0;
            *(float2*)(C + (size_t)(row0 + 8) * ldc + col) = o1;
        }
    }
}

// ---------------- flash attention (ldmatrix everywhere) ----------------------
// grid (16, 64), 256 thr = 8 warps, warp = 16 q-rows. Q frags in regs
// (pre-scaled 1/8). K smem [tok][dh+pad], V smem [dh][tok+pad] (from g_vT),
// P in recycled Q region. All fragment loads via LDSM; stride 68 => conflict-free.
#define F_QP   (128*68)
#define F_KSZ  (64*68)
#define F_STG  (2*F_KSZ)
#define F_KV0  F_QP
#define F_SMEM ((F_QP + 2 * F_STG) * 4)

__global__ __launch_bounds__(256, 2) void flash_kernel(
    const float* __restrict__ qkv, const float* __restrict__ vT,
    float* __restrict__ attn)
{
    extern __shared__ float smf[];
    uint32_t smb = (uint32_t)__cvta_generic_to_shared(smf);
    uint32_t* QP = (uint32_t*)smf;   // Qs during init, Ps afterwards

    int bh = blockIdx.y;
    int b = bh >> 4, h = bh & 15;
    int q0 = blockIdx.x * 128;

    int tid  = threadIdx.x;
    int warp = tid >> 5, lane = tid & 31;
    int q = lane & 3, r = lane >> 2;
    int rb = warp * 16;
    int lane8 = lane & 7, gq = lane >> 3, g2 = gq & 1;

    const float* base  = qkv + (size_t)b * NSEQ * TD + h * (3 * DH);
    const float* vbase = vT + (size_t)bh * DH * NSEQ;

    // ---- load Q tile (x0.125 exact; data already tf32-rounded) ----
    {
        int row = tid >> 1;
        int c0 = (tid & 1) * 32;
        const float* Qp = base + (size_t)(q0 + row) * TD + c0;
#pragma unroll
        for (int i = 0; i < 8; i++) {
            float4 v = *(const float4*)(Qp + i * 4);
            QP[row * 68 + c0 + i * 4 + 0] = __float_as_uint(v.x * 0.125f);
            QP[row * 68 + c0 + i * 4 + 1] = __float_as_uint(v.y * 0.125f);
            QP[row * 68 + c0 + i * 4 + 2] = __float_as_uint(v.z * 0.125f);
            QP[row * 68 + c0 + i * 4 + 3] = __float_as_uint(v.w * 0.125f);
        }
    }

    int kv_row = tid >> 2;             // 0..63
    int kv_c0  = (tid & 3) * 16;       // 0..48

    auto load_kv = [&](int stg, int kt) {
        const float* Kp = base + (size_t)(kt + kv_row) * TD + DH + kv_c0;
        const float* Vp = vbase + (size_t)kv_row * NSEQ + kt + kv_c0;
        uint32_t kd = smb + (uint32_t)(F_KV0 + stg * F_STG + kv_row * 68 + kv_c0) * 4;
        uint32_t vd = kd + (uint32_t)F_KSZ * 4;
#pragma unroll
        for (int i = 0; i < 4; i++) {
            cp16(kd + i * 16, Kp + i * 4);
            cp16(vd + i * 16, Vp + i * 4);
        }
    };

    __syncthreads();                   // Qs written

    uint32_t qf[8][4];
#pragma unroll
    for (int ks = 0; ks < 8; ks++) {
        int k = ks * 8;
        qf[ks][0] = QP[(rb + r) * 68 + k + q];
        qf[ks][1] = QP[(rb + r + 8) * 68 + k + q];
        qf[ks][2] = QP[(rb + r) * 68 + k + q + 4];
        qf[ks][3] = QP[(rb + r + 8) * 68 + k + q + 4];
    }

    load_kv(0, 0);  cp_commit();
    load_kv(1, 64); cp_commit();

    float o[8][4];
#pragma unroll
    for (int nt = 0; nt < 8; nt++)
#pragma unroll
        for (int i = 0; i < 4; i++) o[nt][i] = 0.f;
    float m0 = -1e30f, m1 = -1e30f, l0 = 0.f, l1 = 0.f;

    // ldmatrix address components
    uint32_t kv_r = lane8;                    // row within 8-row block
    uint32_t p_row = rb + lane8 + 8 * (gq & 1);
    uint32_t p_col = 4 * (gq >> 1);

    __syncthreads();                   // Q frags built; QP reusable as Ps

    for (int c = 0; c < NSEQ / 64; c++) {
        cp_wait1();
        __syncthreads();               // stage c%2 ready

        uint32_t kbase = smb + (uint32_t)(F_KV0 + (c & 1) * F_STG) * 4;
        uint32_t vbse  = kbase + (uint32_t)F_KSZ * 4;

        // S = (Q/8) @ K^T
        float s[8][4];
#pragma unroll
        for (int nt = 0; nt < 8; nt++)
#pragma unroll
            for (int i = 0; i < 4; i++) s[nt][i] = 0.f;

#pragma unroll
        for (int ks = 0; ks < 8; ks++) {
#pragma unroll
            for (int nt = 0; nt < 8; nt++) {
                uint32_t bfr[2];
                ldsm2(bfr, kbase + ((nt * 8 + kv_r) * 68 + ks * 8 + 4 * g2) * 4);
                mma_tf32(s[nt], qf[ks], bfr);
            }
        }

        // online softmax
        float mx0 = -1e30f, mx1 = -1e30f;
#pragma unroll
        for (int nt = 0; nt < 8; nt++) {
            mx0 = fmaxf(mx0, fmaxf(s[nt][0], s[nt][1]));
            mx1 = fmaxf(mx1, fmaxf(s[nt][2], s[nt][3]));
        }
#pragma unroll
        for (int off = 1; off <= 2; off <<= 1) {
            mx0 = fmaxf(mx0, __shfl_xor_sync(0xffffffffu, mx0, off));
            mx1 = fmaxf(mx1, __shfl_xor_sync(0xffffffffu, mx1, off));
        }
        float mn0 = fmaxf(m0, mx0), mn1 = fmaxf(m1, mx1);
        float al0 = __expf(m0 - mn0), al1 = __expf(m1 - mn1);
        m0 = mn0; m1 = mn1;

        float sum0 = 0.f, sum1 = 0.f;
#pragma unroll
        for (int nt = 0; nt < 8; nt++) {
            float p0 = __expf(s[nt][0] - m0);
            float p1 = __expf(s[nt][1] - m0);
            float p2 = __expf(s[nt][2] - m1);
            float p3 = __expf(s[nt][3] - m1);
            sum0 += p0 + p1; sum1 += p2 + p3;
            int cc = nt * 8 + 2 * q;
            QP[(rb + r) * 68 + cc]         = f2tf(p0);
            QP[(rb + r) * 68 + cc + 1]     = f2tf(p1);
            QP[(rb + r + 8) * 68 + cc]     = f2tf(p2);
            QP[(rb + r + 8) * 68 + cc + 1] = f2tf(p3);
        }
#pragma unroll
        for (int off = 1; off <= 2; off <<= 1) {
            sum0 += __shfl_xor_sync(0xffffffffu, sum0, off);
            sum1 += __shfl_xor_sync(0xffffffffu, sum1, off);
        }
        l0 = l0 * al0 + sum0;
        l1 = l1 * al1 + sum1;

#pragma unroll
        for (int nt = 0; nt < 8; nt++) {
            o[nt][0] *= al0; o[nt][1] *= al0;
            o[nt][2] *= al1; o[nt][3] *= al1;
        }
        __syncwarp();                  // Ps rows are warp-private

        // O += P @ V   (V in [dh][tok] layout => LDSM-native)
#pragma unroll
        for (int ks = 0; ks < 8; ks++) {
            uint32_t pa[4];
            ldsm4(pa, smb + (p_row * 68 + ks * 8 + p_col) * 4);
#pragma unroll
            for (int nt = 0; nt < 8; nt++) {
                uint32_t bfr[2];
                ldsm2(bfr, vbse + ((nt * 8 + kv_r) * 68 + ks * 8 + 4 * g2) * 4);
                mma_tf32(o[nt], pa, bfr);
            }
        }

        __syncthreads();               // stage c%2 fully consumed
        if (c + 2 < NSEQ / 64) load_kv(c & 1, (c + 2) * 64);
        cp_commit();
    }

    // normalize, round (feeds out-proj MMA), write to [b, n, D]
    float inv0 = 1.f / l0, inv1 = 1.f / l1;
    size_t row0 = (size_t)(b * NSEQ + q0 + rb + r);
#pragma unroll
    for (int nt = 0; nt < 8; nt++) {
        int col = h * DH + nt * 8 + 2 * q;
        float2 v0, v1;
        v0.x = f2tff(o[nt][0] * inv0); v0.y = f2tff(o[nt][1] * inv0);
        v1.x = f2tff(o[nt][2] * inv1); v1.y = f2tff(o[nt][3] * inv1);
        *(float2*)(attn + row0 * D + col) = v0;
        *(float2*)(attn + (row0 + 8) * D + col) = v1;
    }
}

// ---------------- launch -----------------------------------------------------
extern "C" void kernel_launch(void* const* d_in, const int* in_sizes, int n_in,
                              void* d_out, int out_size)
{
    const float* z     = (const float*)d_in[0];
    const float* W_qkv = (const float*)d_in[1];
    const float* b_qkv = (const float*)d_in[2];
    const float* W_msa = (const float*)d_in[3];
    const float* b_msa = (const float*)d_in[4];
    float* out = (float*)d_out;

    float *p_qkv, *p_attn, *p_z, *p_wq, *p_wm, *p_vT;
    cudaGetSymbolAddress((void**)&p_qkv, g_qkv);
    cudaGetSymbolAddress((void**)&p_attn, g_attn);
    cudaGetSymbolAddress((void**)&p_z, g_z);
    cudaGetSymbolAddress((void**)&p_wq, g_wq);
    cudaGetSymbolAddress((void**)&p_wm, g_wm);
    cudaGetSymbolAddress((void**)&p_vT, g_vT);

    cudaFuncSetAttribute(gemm_tf32,
                         cudaFuncAttributeMaxDynamicSharedMemorySize, G_SMEM);
    cudaFuncSetAttribute(flash_kernel,
                         cudaFuncAttributeMaxDynamicSharedMemorySize, F_SMEM);

    // 0) prep: round z; round+transpose weights to [n][k]
    round_kernel<<<(ROWS * D / 4 + 255) / 256, 256>>>(z, p_z, ROWS * D / 4);
    trw_kernel<<<dim3(D / 32, TD / 32), dim3(32, 8)>>>(W_qkv, p_wq, D, TD);
    trw_kernel<<<dim3(D / 32, D / 32), dim3(32, 8)>>>(W_msa, p_wm, D, D);

    // 1) QKV projection (rounded output)
    gemm_tf32<<<dim3(TD / 128, ROWS / 128), 256, G_SMEM>>>(
        ROWS, TD, D, p_z, D, p_wq, D, p_qkv, TD, b_qkv, 1);

    // 1b) transpose V third of qkv into [bh][dh][tok]
    vT_kernel<<<dim3(NSEQ / 32, 2 * BHN), dim3(32, 8)>>>(p_qkv, p_vT);

    // 2) fused flash attention -> [b, n, D] (rounded output)
    flash_kernel<<<dim3(NSEQ / 128, BHN), 256, F_SMEM>>>(p_qkv, p_vT, p_attn);

    // 3) output projection (final: not rounded)
    gemm_tf32<<<dim3(D / 128, ROWS / 128), 256, G_SMEM>>>(
        ROWS, D, D, p_attn, D, p_wm, D, out, D, b_msa, 0);
}